// round 10
// baseline (speedup 1.0000x reference)
#include <cuda_runtime.h>
#include <math.h>

#define B_   4096
#define S_   32
#define D_   512
#define V_   32000
#define H_   256

#define NB_TR   32
#define NB_SL   B_
#define NB_ML   (B_ / 16)           // 256
#define NB_EN   B_
#define BID_SL  NB_TR               // 32
#define BID_MIX (BID_SL + NB_SL)    // 4128: mixed entropy/mlp region, 17-cycle
#define NB_MIX  (NB_EN + NB_ML)     // 4352 = 17 * 256
#define NB_ALL  (BID_MIX + NB_MIX)  // 8480

__device__ float g_xn[B_ * D_];           // LayerNormed slot means [B, D]
__device__ float g_w1t[D_ * H_];          // w1 transposed [k][j]
__device__ float g_acc[8];                // [0..3] probs, [4] entropy, [5] norms
__device__ int   g_w1t_done, g_done;
__device__ int   g_slots_done[B_ / 16];   // 256 group counters

// ---------------------------------------------------------------- K_init
__global__ __launch_bounds__(512) void k_init() {
    int t = threadIdx.x;
    if (t < 256) g_slots_done[t] = 0;
    else if (t < 264) g_acc[t - 256] = 0.f;
    else if (t == 264) g_w1t_done = 0;
    else if (t == 265) g_done = 0;
}

// ---------------------------------------------------------------- MEGA
__global__ __launch_bounds__(512, 4) void k_mega(const float* __restrict__ slots,
                                                 const float* __restrict__ logits,
                                                 const float* __restrict__ ln_w,
                                                 const float* __restrict__ ln_b,
                                                 const float* __restrict__ w1,
                                                 const float* __restrict__ b1,
                                                 const float* __restrict__ w2,
                                                 const float* __restrict__ b2,
                                                 float* __restrict__ out) {
    __shared__ union {
        float tr[64][65];                                   // transpose ~16.6 KB
        __align__(16) float stage[16][D_];                  // slots 32 KB
        struct {                                            // mlp ~36 KB
            __align__(16) float As[32][20];
            __align__(16) float Bs[32][260];
            float sh_p[16][4];
            float sdec[4];
        } m;
    } u;
    __shared__ float r1[16], r2[16], r3[16];
    __shared__ float s_mu, s_rstd;
    __shared__ int s_flag;

    int bid = blockIdx.x, tid = threadIdx.x;
    int w = tid >> 5, l = tid & 31;

    // mixed-region decode: every 17th block (pos 16 of each 17-cycle) is mlp
    int q = bid - BID_MIX;            // valid when bid >= BID_MIX
    int cyc = q / 17, pos = q % 17;

    if (bid < BID_SL) {
        // ===================== w1t transpose [H,D]->[D,H], 64x64 tiles
        int k0 = (bid & 7) * 64, j0 = (bid >> 3) * 64;
        int x = tid & 63, y = tid >> 6;
#pragma unroll
        for (int r = 0; r < 64; r += 8)
            u.tr[y + r][x] = w1[(size_t)(j0 + y + r) * D_ + k0 + x];
        __syncthreads();
#pragma unroll
        for (int r = 0; r < 64; r += 8)
            g_w1t[(size_t)(k0 + y + r) * H_ + j0 + x] = u.tr[x][y + r];
        __threadfence();
        __syncthreads();
        if (tid == 0) atomicAdd(&g_w1t_done, 1);

    } else if (bid < BID_MIX) {
        // ===================== slots + LN (proven body)
        int b = bid - BID_SL;
        const float4* base = (const float4*)(slots + (size_t)b * (S_ * D_));
        float4 xa[4];
        float sq0 = 0.f, sq1 = 0.f;
#pragma unroll
        for (int i = 0; i < 4; ++i) {
            int f4 = i * 32 + l;
            float4 v0 = __ldcs(&base[(2 * w) * 128 + f4]);
            float4 v1 = __ldcs(&base[(2 * w + 1) * 128 + f4]);
            sq0 += v0.x*v0.x + v0.y*v0.y + v0.z*v0.z + v0.w*v0.w;
            sq1 += v1.x*v1.x + v1.y*v1.y + v1.z*v1.z + v1.w*v1.w;
            xa[i].x = v0.x + v1.x; xa[i].y = v0.y + v1.y;
            xa[i].z = v0.z + v1.z; xa[i].w = v0.w + v1.w;
        }
#pragma unroll
        for (int i = 0; i < 4; ++i)
            *(float4*)&u.stage[w][(i * 32 + l) * 4] = xa[i];
#pragma unroll
        for (int o = 16; o; o >>= 1) {
            sq0 += __shfl_xor_sync(0xffffffffu, sq0, o);
            sq1 += __shfl_xor_sync(0xffffffffu, sq1, o);
        }
        float v3 = (l == 0) ? (sqrtf(sq0) + sqrtf(sq1)) : 0.f;
        __syncthreads();

        int d = tid;
        float xs = 0.f;
#pragma unroll
        for (int ww = 0; ww < 16; ++ww) xs += u.stage[ww][d];
        float x = xs * (1.f / 32.f);

        float a1 = x, a2 = x * x, a3 = v3;
#pragma unroll
        for (int o = 16; o; o >>= 1) {
            a1 += __shfl_xor_sync(0xffffffffu, a1, o);
            a2 += __shfl_xor_sync(0xffffffffu, a2, o);
            a3 += __shfl_xor_sync(0xffffffffu, a3, o);
        }
        if (l == 0) { r1[w] = a1; r2[w] = a2; r3[w] = a3; }
        __syncthreads();
        if (w == 0) {
            float c1 = (l < 16) ? r1[l] : 0.f;
            float c2 = (l < 16) ? r2[l] : 0.f;
            float c3 = (l < 16) ? r3[l] : 0.f;
#pragma unroll
            for (int o = 8; o; o >>= 1) {
                c1 += __shfl_xor_sync(0xffffffffu, c1, o);
                c2 += __shfl_xor_sync(0xffffffffu, c2, o);
                c3 += __shfl_xor_sync(0xffffffffu, c3, o);
            }
            if (l == 0) {
                float mu = c1 * (1.f / (float)D_);
                float var = c2 * (1.f / (float)D_) - mu * mu;
                s_mu = mu;
                s_rstd = rsqrtf(var + 1e-5f);
                atomicAdd(&g_acc[5], c3);
            }
        }
        __syncthreads();
        g_xn[(size_t)b * D_ + tid] = (x - s_mu) * s_rstd * ln_w[tid] + ln_b[tid];
        __threadfence();
        __syncthreads();
        if (tid == 0) atomicAdd(&g_slots_done[b >> 4], 1);

    } else if (pos < 16) {
        // ===================== entropy row (proven body; m=0)
        int b = cyc * 16 + pos;
        const float4* row = (const float4*)(logits + (size_t)b * V_);
        float Z0 = 0.f, T0 = 0.f, Z1 = 0.f, T1 = 0.f;
#pragma unroll 2
        for (int i = tid; i < V_ / 4; i += 512) {
            float4 v = __ldcs(&row[i]);
            float e0 = __expf(v.x), e1 = __expf(v.y), e2 = __expf(v.z), e3 = __expf(v.w);
            Z0 += e0 + e2;  Z1 += e1 + e3;
            T0 = fmaf(e0, v.x, T0); T1 = fmaf(e1, v.y, T1);
            T0 = fmaf(e2, v.z, T0); T1 = fmaf(e3, v.w, T1);
        }
        float Z = Z0 + Z1, T = T0 + T1;
#pragma unroll
        for (int o = 16; o; o >>= 1) {
            Z += __shfl_xor_sync(0xffffffffu, Z, o);
            T += __shfl_xor_sync(0xffffffffu, T, o);
        }
        if (l == 0) { r1[w] = Z; r2[w] = T; }
        __syncthreads();
        if (w == 0) {
            float ZZ = (l < 16) ? r1[l] : 0.f;
            float TT = (l < 16) ? r2[l] : 0.f;
#pragma unroll
            for (int o = 8; o; o >>= 1) {
                ZZ += __shfl_xor_sync(0xffffffffu, ZZ, o);
                TT += __shfl_xor_sync(0xffffffffu, TT, o);
            }
            if (l == 0) atomicAdd(&g_acc[4], logf(ZZ) - TT / ZZ);
        }

    } else {
        // ===================== mlp: BM=16, BN=256, BK=32 + fused sigmoid (proven body)
        int g = cyc;                          // 0..255
        int b0 = g * 16;

        if (tid == 0) {
            while (*((volatile int*)&g_w1t_done) < NB_TR) __nanosleep(32);
            while (((volatile int*)g_slots_done)[g] < 16) __nanosleep(32);
        }
        __syncthreads();
        __threadfence();

        if (tid < 64) ((float*)u.m.sh_p)[tid] = 0.f;
        if (tid < 4) u.m.sdec[tid] = 0.f;
        __syncthreads();

        int ty = tid >> 6;        // 0..7 -> rows {2ty, 2ty+1}
        int tx = tid & 63;        // 0..63 -> cols 4tx..4tx+3

        float acc[2][4];
#pragma unroll
        for (int i = 0; i < 2; ++i)
#pragma unroll
            for (int j = 0; j < 4; ++j) acc[i][j] = 0.f;

        for (int kk = 0; kk < D_; kk += 32) {
            u.m.As[tid & 31][tid >> 5] = g_xn[(size_t)(b0 + (tid >> 5)) * D_ + kk + (tid & 31)];
#pragma unroll
            for (int rep = 0; rep < 4; ++rep) {
                int qq = rep * 512 + tid;
                int k = qq >> 6, c4 = qq & 63;
                *(float4*)&u.m.Bs[k][4 * c4] =
                    *(const float4*)&g_w1t[(size_t)(kk + k) * H_ + 4 * c4];
            }
            __syncthreads();
#pragma unroll
            for (int c = 0; c < 32; ++c) {
                float2 a  = *(const float2*)&u.m.As[c][ty * 2];
                float4 bv = *(const float4*)&u.m.Bs[c][tx * 4];
                acc[0][0] = fmaf(a.x, bv.x, acc[0][0]); acc[0][1] = fmaf(a.x, bv.y, acc[0][1]);
                acc[0][2] = fmaf(a.x, bv.z, acc[0][2]); acc[0][3] = fmaf(a.x, bv.w, acc[0][3]);
                acc[1][0] = fmaf(a.y, bv.x, acc[1][0]); acc[1][1] = fmaf(a.y, bv.y, acc[1][1]);
                acc[1][2] = fmaf(a.y, bv.z, acc[1][2]); acc[1][3] = fmaf(a.y, bv.w, acc[1][3]);
            }
            __syncthreads();
        }

#pragma unroll
        for (int i = 0; i < 2; ++i) {
            int r = ty * 2 + i;
            float p[4] = {0.f, 0.f, 0.f, 0.f};
#pragma unroll
            for (int jj = 0; jj < 4; ++jj) {
                int jg = tx * 4 + jj;
                float hp = acc[i][jj] + b1[jg];
                float gl = 0.5f * hp * (1.f + erff(hp * 0.70710678118654752f));
#pragma unroll
                for (int k = 0; k < 4; ++k) p[k] = fmaf(gl, w2[k * H_ + jg], p[k]);
            }
#pragma unroll
            for (int k = 0; k < 4; ++k) {
#pragma unroll
                for (int o = 16; o; o >>= 1)
                    p[k] += __shfl_xor_sync(0xffffffffu, p[k], o);
                if (l == 0) atomicAdd(&u.m.sh_p[r][k], p[k]);   // 2 warps per row
            }
        }
        __syncthreads();
        if (tid < 64) {
            int r = tid >> 2, k = tid & 3;
            float z = u.m.sh_p[r][k] + b2[k];
            float s = 1.f / (1.f + __expf(-z));
            atomicAdd(&u.m.sdec[k], s);
        }
        __syncthreads();
        if (tid < 4) atomicAdd(&g_acc[tid], u.m.sdec[tid]);
    }

    // ===================== completion: last block packs outputs
    __syncthreads();
    if (tid == 0) {
        __threadfence();
        s_flag = (atomicAdd(&g_done, 1) == NB_ALL - 1);
    }
    __syncthreads();
    if (s_flag) {
        __threadfence();
        volatile float* ga = g_acc;
        if (tid < 4)       out[tid] = ga[tid] * (1.f / (float)B_);
        else if (tid == 4) out[4] = ga[4] * (1.f / (float)B_);
        else if (tid == 5) out[5] = ga[5] * (1.f / (float)(B_ * S_));
    }
}

// ---------------------------------------------------------------- launch
extern "C" void kernel_launch(void* const* d_in, const int* in_sizes, int n_in,
                              void* d_out, int out_size) {
    const float* slots  = (const float*)d_in[0];
    const float* logits = (const float*)d_in[1];
    const float* ln_w   = (const float*)d_in[2];
    const float* ln_b   = (const float*)d_in[3];
    const float* w1     = (const float*)d_in[4];
    const float* b1     = (const float*)d_in[5];
    const float* w2     = (const float*)d_in[6];
    const float* b2     = (const float*)d_in[7];
    float* out = (float*)d_out;

    k_init<<<1, 512>>>();
    k_mega<<<NB_ALL, 512>>>(slots, logits, ln_w, ln_b, w1, b1, w2, b2, out);
}

// round 11
// speedup vs baseline: 1.0168x; 1.0168x over previous
#include <cuda_runtime.h>
#include <math.h>

#define B_   4096
#define S_   32
#define D_   512
#define V_   32000
#define H_   256

#define NB_TR   32
#define BID_FU  NB_TR              // fused blocks start
#define NB_FU   B_                 // 4096 fused slots+entropy blocks
#define NB_ALL  (BID_FU + NB_FU)   // 4128

__device__ float g_xn[B_ * D_];           // LayerNormed slot means [B, D]
__device__ float g_w1t[D_ * H_];          // w1 transposed [k][j]
__device__ float g_acc[8];                // [0..3] probs, [4] entropy, [5] norms
__device__ int   g_w1t_done, g_done;
__device__ int   g_slots_done[B_ / 16];   // 256 group counters

// ---------------------------------------------------------------- K_init
__global__ __launch_bounds__(512) void k_init() {
    int t = threadIdx.x;
    if (t < 256) g_slots_done[t] = 0;
    else if (t < 264) g_acc[t - 256] = 0.f;
    else if (t == 264) g_w1t_done = 0;
    else if (t == 265) g_done = 0;
}

// ---------------------------------------------------------------- MEGA: homogeneous fused blocks
__global__ __launch_bounds__(512, 4) void k_mega(const float* __restrict__ slots,
                                                 const float* __restrict__ logits,
                                                 const float* __restrict__ ln_w,
                                                 const float* __restrict__ ln_b,
                                                 const float* __restrict__ w1,
                                                 const float* __restrict__ b1,
                                                 const float* __restrict__ w2,
                                                 const float* __restrict__ b2,
                                                 float* __restrict__ out) {
    __shared__ union {
        float tr[64][65];                                   // transpose ~16.6 KB
        __align__(16) float stage[16][D_];                  // slots 32 KB
        struct {                                            // mlp ~36 KB
            __align__(16) float As[32][20];
            __align__(16) float Bs[32][260];
            float sh_p[16][4];
            float sdec[4];
        } m;
    } u;
    __shared__ float r1[16], r2[16], r3[16];
    __shared__ float s_mu, s_rstd;
    __shared__ int s_flag;

    int bid = blockIdx.x, tid = threadIdx.x;
    int w = tid >> 5, l = tid & 31;

    if (bid < NB_TR) {
        // ===================== w1t transpose [H,D]->[D,H], 64x64 tiles
        int k0 = (bid & 7) * 64, j0 = (bid >> 3) * 64;
        int x = tid & 63, y = tid >> 6;
#pragma unroll
        for (int r = 0; r < 64; r += 8)
            u.tr[y + r][x] = w1[(size_t)(j0 + y + r) * D_ + k0 + x];
        __syncthreads();
#pragma unroll
        for (int r = 0; r < 64; r += 8)
            g_w1t[(size_t)(k0 + y + r) * H_ + j0 + x] = u.tr[x][y + r];
        __threadfence();
        __syncthreads();
        if (tid == 0) atomicAdd(&g_w1t_done, 1);

    } else {
        int b = bid - BID_FU;

        // ===================== phase A: slots + LN for batch b (proven R2 body)
        {
            const float4* base = (const float4*)(slots + (size_t)b * (S_ * D_));
            float4 xa[4];
            float sq0 = 0.f, sq1 = 0.f;
#pragma unroll
            for (int i = 0; i < 4; ++i) {
                int f4 = i * 32 + l;
                float4 v0 = __ldcs(&base[(2 * w) * 128 + f4]);
                float4 v1 = __ldcs(&base[(2 * w + 1) * 128 + f4]);
                sq0 += v0.x*v0.x + v0.y*v0.y + v0.z*v0.z + v0.w*v0.w;
                sq1 += v1.x*v1.x + v1.y*v1.y + v1.z*v1.z + v1.w*v1.w;
                xa[i].x = v0.x + v1.x; xa[i].y = v0.y + v1.y;
                xa[i].z = v0.z + v1.z; xa[i].w = v0.w + v1.w;
            }
#pragma unroll
            for (int i = 0; i < 4; ++i)
                *(float4*)&u.stage[w][(i * 32 + l) * 4] = xa[i];
#pragma unroll
            for (int o = 16; o; o >>= 1) {
                sq0 += __shfl_xor_sync(0xffffffffu, sq0, o);
                sq1 += __shfl_xor_sync(0xffffffffu, sq1, o);
            }
            float v3 = (l == 0) ? (sqrtf(sq0) + sqrtf(sq1)) : 0.f;
            __syncthreads();

            float xs = 0.f;
#pragma unroll
            for (int ww = 0; ww < 16; ++ww) xs += u.stage[ww][tid];
            float x = xs * (1.f / 32.f);

            float a1 = x, a2 = x * x, a3 = v3;
#pragma unroll
            for (int o = 16; o; o >>= 1) {
                a1 += __shfl_xor_sync(0xffffffffu, a1, o);
                a2 += __shfl_xor_sync(0xffffffffu, a2, o);
                a3 += __shfl_xor_sync(0xffffffffu, a3, o);
            }
            if (l == 0) { r1[w] = a1; r2[w] = a2; r3[w] = a3; }
            __syncthreads();
            if (w == 0) {
                float c1 = (l < 16) ? r1[l] : 0.f;
                float c2 = (l < 16) ? r2[l] : 0.f;
                float c3 = (l < 16) ? r3[l] : 0.f;
#pragma unroll
                for (int o = 8; o; o >>= 1) {
                    c1 += __shfl_xor_sync(0xffffffffu, c1, o);
                    c2 += __shfl_xor_sync(0xffffffffu, c2, o);
                    c3 += __shfl_xor_sync(0xffffffffu, c3, o);
                }
                if (l == 0) {
                    float mu = c1 * (1.f / (float)D_);
                    float var = c2 * (1.f / (float)D_) - mu * mu;
                    s_mu = mu;
                    s_rstd = rsqrtf(var + 1e-5f);
                    atomicAdd(&g_acc[5], c3);
                }
            }
            __syncthreads();
            g_xn[(size_t)b * D_ + tid] = (x - s_mu) * s_rstd * ln_w[tid] + ln_b[tid];
            __threadfence();
            __syncthreads();
            if (tid == 0) atomicAdd(&g_slots_done[b >> 4], 1);
        }

        // ===================== phase B: entropy row b (proven body; m=0)
        {
            const float4* row = (const float4*)(logits + (size_t)b * V_);
            float Z0 = 0.f, T0 = 0.f, Z1 = 0.f, T1 = 0.f;
#pragma unroll 2
            for (int i = tid; i < V_ / 4; i += 512) {
                float4 v = __ldcs(&row[i]);
                float e0 = __expf(v.x), e1 = __expf(v.y), e2 = __expf(v.z), e3 = __expf(v.w);
                Z0 += e0 + e2;  Z1 += e1 + e3;
                T0 = fmaf(e0, v.x, T0); T1 = fmaf(e1, v.y, T1);
                T0 = fmaf(e2, v.z, T0); T1 = fmaf(e3, v.w, T1);
            }
            float Z = Z0 + Z1, T = T0 + T1;
#pragma unroll
            for (int o = 16; o; o >>= 1) {
                Z += __shfl_xor_sync(0xffffffffu, Z, o);
                T += __shfl_xor_sync(0xffffffffu, T, o);
            }
            if (l == 0) { r1[w] = Z; r2[w] = T; }
            __syncthreads();
            if (w == 0) {
                float ZZ = (l < 16) ? r1[l] : 0.f;
                float TT = (l < 16) ? r2[l] : 0.f;
#pragma unroll
                for (int o = 8; o; o >>= 1) {
                    ZZ += __shfl_xor_sync(0xffffffffu, ZZ, o);
                    TT += __shfl_xor_sync(0xffffffffu, TT, o);
                }
                if (l == 0) atomicAdd(&g_acc[4], logf(ZZ) - TT / ZZ);
            }
        }

        // ===================== phase C (1/16 blocks): mlp for group b>>4 (proven body)
        if ((b & 15) == 15) {
            int g = b >> 4;
            int b0 = g * 16;

            if (tid == 0) {
                while (*((volatile int*)&g_w1t_done) < NB_TR) __nanosleep(32);
                while (((volatile int*)g_slots_done)[g] < 16) __nanosleep(32);
            }
            __syncthreads();
            __threadfence();

            if (tid < 64) ((float*)u.m.sh_p)[tid] = 0.f;
            if (tid < 4) u.m.sdec[tid] = 0.f;
            __syncthreads();

            int ty = tid >> 6;        // 0..7 -> rows {2ty, 2ty+1}
            int tx = tid & 63;        // 0..63 -> cols 4tx..4tx+3

            float acc[2][4];
#pragma unroll
            for (int i = 0; i < 2; ++i)
#pragma unroll
                for (int j = 0; j < 4; ++j) acc[i][j] = 0.f;

            for (int kk = 0; kk < D_; kk += 32) {
                u.m.As[tid & 31][tid >> 5] =
                    g_xn[(size_t)(b0 + (tid >> 5)) * D_ + kk + (tid & 31)];
#pragma unroll
                for (int rep = 0; rep < 4; ++rep) {
                    int qq = rep * 512 + tid;
                    int k = qq >> 6, c4 = qq & 63;
                    *(float4*)&u.m.Bs[k][4 * c4] =
                        *(const float4*)&g_w1t[(size_t)(kk + k) * H_ + 4 * c4];
                }
                __syncthreads();
#pragma unroll
                for (int c = 0; c < 32; ++c) {
                    float2 a  = *(const float2*)&u.m.As[c][ty * 2];
                    float4 bv = *(const float4*)&u.m.Bs[c][tx * 4];
                    acc[0][0] = fmaf(a.x, bv.x, acc[0][0]); acc[0][1] = fmaf(a.x, bv.y, acc[0][1]);
                    acc[0][2] = fmaf(a.x, bv.z, acc[0][2]); acc[0][3] = fmaf(a.x, bv.w, acc[0][3]);
                    acc[1][0] = fmaf(a.y, bv.x, acc[1][0]); acc[1][1] = fmaf(a.y, bv.y, acc[1][1]);
                    acc[1][2] = fmaf(a.y, bv.z, acc[1][2]); acc[1][3] = fmaf(a.y, bv.w, acc[1][3]);
                }
                __syncthreads();
            }

#pragma unroll
            for (int i = 0; i < 2; ++i) {
                int r = ty * 2 + i;
                float p[4] = {0.f, 0.f, 0.f, 0.f};
#pragma unroll
                for (int jj = 0; jj < 4; ++jj) {
                    int jg = tx * 4 + jj;
                    float hp = acc[i][jj] + b1[jg];
                    float gl = 0.5f * hp * (1.f + erff(hp * 0.70710678118654752f));
#pragma unroll
                    for (int k = 0; k < 4; ++k) p[k] = fmaf(gl, w2[k * H_ + jg], p[k]);
                }
#pragma unroll
                for (int k = 0; k < 4; ++k) {
#pragma unroll
                    for (int o = 16; o; o >>= 1)
                        p[k] += __shfl_xor_sync(0xffffffffu, p[k], o);
                    if (l == 0) atomicAdd(&u.m.sh_p[r][k], p[k]);   // 2 warps per row
                }
            }
            __syncthreads();
            if (tid < 64) {
                int r = tid >> 2, k = tid & 3;
                float z = u.m.sh_p[r][k] + b2[k];
                float s = 1.f / (1.f + __expf(-z));
                atomicAdd(&u.m.sdec[k], s);
            }
            __syncthreads();
            if (tid < 4) atomicAdd(&g_acc[tid], u.m.sdec[tid]);
        }
    }

    // ===================== completion: last block packs outputs
    __syncthreads();
    if (tid == 0) {
        __threadfence();
        s_flag = (atomicAdd(&g_done, 1) == NB_ALL - 1);
    }
    __syncthreads();
    if (s_flag) {
        __threadfence();
        volatile float* ga = g_acc;
        if (tid < 4)       out[tid] = ga[tid] * (1.f / (float)B_);
        else if (tid == 4) out[4] = ga[4] * (1.f / (float)B_);
        else if (tid == 5) out[5] = ga[5] * (1.f / (float)(B_ * S_));
    }
}

// ---------------------------------------------------------------- launch
extern "C" void kernel_launch(void* const* d_in, const int* in_sizes, int n_in,
                              void* d_out, int out_size) {
    const float* slots  = (const float*)d_in[0];
    const float* logits = (const float*)d_in[1];
    const float* ln_w   = (const float*)d_in[2];
    const float* ln_b   = (const float*)d_in[3];
    const float* w1     = (const float*)d_in[4];
    const float* b1     = (const float*)d_in[5];
    const float* w2     = (const float*)d_in[6];
    const float* b2     = (const float*)d_in[7];
    float* out = (float*)d_out;

    k_init<<<1, 512>>>();
    k_mega<<<NB_ALL, 512>>>(slots, logits, ln_w, ln_b, w1, b1, w2, b2, out);
}

// round 12
// speedup vs baseline: 1.5300x; 1.5046x over previous
#include <cuda_runtime.h>
#include <math.h>

#define B_   4096
#define S_   32
#define D_   512
#define V_   32000
#define H_   256

#define NB_TR   32
#define GRID_SL (NB_TR + B_)       // 4128: transpose + slots
#define NB_ML   512                // mlp blocks (BM=16, BN=128, 2 per group)
#define GRID_MG (NB_ML + B_)       // 4608: mlp + entropy

__device__ float g_xn[B_ * D_];           // LayerNormed slot means [B, D]
__device__ float g_w1t[D_ * H_];          // w1 transposed [k][j]
__device__ float g_p[B_ * 4];             // pre-sigmoid layer2 accumulators
__device__ float g_acc[8];                // [0..3] probs, [4] entropy, [5] norms
__device__ int   g_done;
__device__ int   g_grp_done[B_ / 16];     // 256

// ---------------------------------------------------------------- K_init
__global__ __launch_bounds__(512) void k_init() {
    int i = blockIdx.x * 512 + threadIdx.x;
    if (i < B_ * 4) g_p[i] = 0.f;
    if (i < 256) g_grp_done[i] = 0;
    if (blockIdx.x == 0) {
        if (threadIdx.x < 8) g_acc[threadIdx.x] = 0.f;
        if (threadIdx.x == 8) g_done = 0;
    }
}

// ---------------------------------------------------------------- K1: w1t transpose + slots (512 thr)
__global__ __launch_bounds__(512, 4) void k_slots(const float* __restrict__ slots,
                                                  const float* __restrict__ ln_w,
                                                  const float* __restrict__ ln_b,
                                                  const float* __restrict__ w1) {
    __shared__ union {
        float tr[64][65];                   // ~16.6 KB
        __align__(16) float stage[16][D_];  // 32 KB
    } u;
    __shared__ float r1[16], r2[16], r3[16];
    __shared__ float s_mu, s_rstd;

    int bid = blockIdx.x, tid = threadIdx.x;
    int w = tid >> 5, l = tid & 31;

    if (bid < NB_TR) {
        // w1 [H,D] -> g_w1t [D,H], 64x64 tiles (8 k-tiles x 4 j-tiles)
        int k0 = (bid & 7) * 64, j0 = (bid >> 3) * 64;
        int x = tid & 63, y = tid >> 6;
#pragma unroll
        for (int r = 0; r < 64; r += 8)
            u.tr[y + r][x] = w1[(size_t)(j0 + y + r) * D_ + k0 + x];
        __syncthreads();
#pragma unroll
        for (int r = 0; r < 64; r += 8)
            g_w1t[(size_t)(k0 + y + r) * H_ + j0 + x] = u.tr[x][y + r];
        return;
    }

    // ----- slots + LN (R2 proven body, untouched)
    int b = bid - NB_TR;
    const float4* base = (const float4*)(slots + (size_t)b * (S_ * D_));
    float4 xa[4];
    float sq0 = 0.f, sq1 = 0.f;
#pragma unroll
    for (int i = 0; i < 4; ++i) {
        int f4 = i * 32 + l;
        float4 v0 = __ldcs(&base[(2 * w) * 128 + f4]);
        float4 v1 = __ldcs(&base[(2 * w + 1) * 128 + f4]);
        sq0 += v0.x*v0.x + v0.y*v0.y + v0.z*v0.z + v0.w*v0.w;
        sq1 += v1.x*v1.x + v1.y*v1.y + v1.z*v1.z + v1.w*v1.w;
        xa[i].x = v0.x + v1.x; xa[i].y = v0.y + v1.y;
        xa[i].z = v0.z + v1.z; xa[i].w = v0.w + v1.w;
    }
#pragma unroll
    for (int i = 0; i < 4; ++i)
        *(float4*)&u.stage[w][(i * 32 + l) * 4] = xa[i];
#pragma unroll
    for (int o = 16; o; o >>= 1) {
        sq0 += __shfl_xor_sync(0xffffffffu, sq0, o);
        sq1 += __shfl_xor_sync(0xffffffffu, sq1, o);
    }
    float v3 = (l == 0) ? (sqrtf(sq0) + sqrtf(sq1)) : 0.f;
    __syncthreads();

    float xs = 0.f;
#pragma unroll
    for (int ww = 0; ww < 16; ++ww) xs += u.stage[ww][tid];
    float x = xs * (1.f / 32.f);

    float a1 = x, a2 = x * x, a3 = v3;
#pragma unroll
    for (int o = 16; o; o >>= 1) {
        a1 += __shfl_xor_sync(0xffffffffu, a1, o);
        a2 += __shfl_xor_sync(0xffffffffu, a2, o);
        a3 += __shfl_xor_sync(0xffffffffu, a3, o);
    }
    if (l == 0) { r1[w] = a1; r2[w] = a2; r3[w] = a3; }
    __syncthreads();
    if (w == 0) {
        float c1 = (l < 16) ? r1[l] : 0.f;
        float c2 = (l < 16) ? r2[l] : 0.f;
        float c3 = (l < 16) ? r3[l] : 0.f;
#pragma unroll
        for (int o = 8; o; o >>= 1) {
            c1 += __shfl_xor_sync(0xffffffffu, c1, o);
            c2 += __shfl_xor_sync(0xffffffffu, c2, o);
            c3 += __shfl_xor_sync(0xffffffffu, c3, o);
        }
        if (l == 0) {
            float mu = c1 * (1.f / (float)D_);
            float var = c2 * (1.f / (float)D_) - mu * mu;
            s_mu = mu;
            s_rstd = rsqrtf(var + 1e-5f);
            atomicAdd(&g_acc[5], c3);
        }
    }
    __syncthreads();
    g_xn[(size_t)b * D_ + tid] = (x - s_mu) * s_rstd * ln_w[tid] + ln_b[tid];
}

// ---------------------------------------------------------------- K2: mlp + entropy (256 thr)
__global__ __launch_bounds__(256, 8) void k_mega(const float* __restrict__ logits,
                                                 const float* __restrict__ b1,
                                                 const float* __restrict__ w2,
                                                 const float* __restrict__ b2,
                                                 float* __restrict__ out) {
    __shared__ union {
        struct {                                            // mlp ~19.2 KB
            __align__(16) float As[32][20];
            __align__(16) float Bs[32][132];
            float sh_p[16][4];
        } m;
        struct { float Z[8], T[8]; } e;                     // entropy
    } u;
    __shared__ int s_flag;

    int bid = blockIdx.x, tid = threadIdx.x;
    int w = tid >> 5, l = tid & 31;

    if (bid < NB_ML) {
        // ===================== mlp (R2 proven body: BM=16, BN=128, BK=32, 2x4)
        int g = bid;                  // 0..511
        int grp = g >> 1;
        int b0 = grp * 16;
        int n0 = (g & 1) * 128;

        if (tid < 64) ((float*)u.m.sh_p)[tid] = 0.f;

        int ty = tid >> 5;            // 0..7 -> rows {2ty, 2ty+1}
        int tx = tid & 31;            // cols 4tx..4tx+3

        float acc[2][4];
#pragma unroll
        for (int i = 0; i < 2; ++i)
#pragma unroll
            for (int j = 0; j < 4; ++j) acc[i][j] = 0.f;

        for (int kk = 0; kk < D_; kk += 32) {
#pragma unroll
            for (int rep = 0; rep < 2; ++rep) {
                int e = tid + rep * 256;
                u.m.As[e & 31][e >> 5] = g_xn[(size_t)(b0 + (e >> 5)) * D_ + kk + (e & 31)];
            }
#pragma unroll
            for (int rep = 0; rep < 4; ++rep) {
                int qq = rep * 256 + tid;
                int k = qq >> 5, c4 = qq & 31;
                *(float4*)&u.m.Bs[k][4 * c4] =
                    *(const float4*)&g_w1t[(size_t)(kk + k) * H_ + n0 + 4 * c4];
            }
            __syncthreads();
#pragma unroll
            for (int c = 0; c < 32; ++c) {
                float2 a  = *(const float2*)&u.m.As[c][ty * 2];
                float4 bv = *(const float4*)&u.m.Bs[c][tx * 4];
                acc[0][0] = fmaf(a.x, bv.x, acc[0][0]); acc[0][1] = fmaf(a.x, bv.y, acc[0][1]);
                acc[0][2] = fmaf(a.x, bv.z, acc[0][2]); acc[0][3] = fmaf(a.x, bv.w, acc[0][3]);
                acc[1][0] = fmaf(a.y, bv.x, acc[1][0]); acc[1][1] = fmaf(a.y, bv.y, acc[1][1]);
                acc[1][2] = fmaf(a.y, bv.z, acc[1][2]); acc[1][3] = fmaf(a.y, bv.w, acc[1][3]);
            }
            __syncthreads();
        }

#pragma unroll
        for (int i = 0; i < 2; ++i) {
            int r = ty * 2 + i;
            float p[4] = {0.f, 0.f, 0.f, 0.f};
#pragma unroll
            for (int jj = 0; jj < 4; ++jj) {
                int jg = n0 + tx * 4 + jj;
                float hp = acc[i][jj] + b1[jg];
                float gl = 0.5f * hp * (1.f + erff(hp * 0.70710678118654752f));
#pragma unroll
                for (int k = 0; k < 4; ++k) p[k] = fmaf(gl, w2[k * H_ + jg], p[k]);
            }
#pragma unroll
            for (int k = 0; k < 4; ++k) {
#pragma unroll
                for (int o = 16; o; o >>= 1)
                    p[k] += __shfl_xor_sync(0xffffffffu, p[k], o);
                if (tx == 0) u.m.sh_p[r][k] = p[k];
            }
        }
        __syncthreads();
        if (tid < 64) {
            int r = tid >> 2, k = tid & 3;
            atomicAdd(&g_p[(size_t)(b0 + r) * 4 + k], u.m.sh_p[r][k]);
        }
        __threadfence();
        __syncthreads();
        if (tid == 0) s_flag = (atomicAdd(&g_grp_done[grp], 1) == 1);
        __syncthreads();
        if (s_flag) {                 // second finisher: sigmoid + batch partial
            __threadfence();
            if (tid < 64) {
                int r = tid >> 2, k = tid & 3;
                float z = __ldcg(&g_p[(size_t)(b0 + r) * 4 + k]) + b2[k];
                float s = 1.f / (1.f + __expf(-z));
#pragma unroll
                for (int o = 4; o <= 16; o <<= 1)
                    s += __shfl_xor_sync(0xffffffffu, s, o);   // sum same-k rows in warp
                if ((tid & 31) < 4) atomicAdd(&g_acc[tid & 31], s);
            }
        }

    } else {
        // ===================== entropy (R3 proven body: 256 thr, unroll 4, m=0)
        int b = bid - NB_ML;
        const float4* row = (const float4*)(logits + (size_t)b * V_);
        float Z0 = 0.f, T0 = 0.f, Z1 = 0.f, T1 = 0.f;
#pragma unroll 4
        for (int i = tid; i < V_ / 4; i += 256) {
            float4 v = __ldcs(&row[i]);
            float e0 = __expf(v.x), e1 = __expf(v.y), e2 = __expf(v.z), e3 = __expf(v.w);
            Z0 += e0 + e2;  Z1 += e1 + e3;
            T0 = fmaf(e0, v.x, T0); T1 = fmaf(e1, v.y, T1);
            T0 = fmaf(e2, v.z, T0); T1 = fmaf(e3, v.w, T1);
        }
        float Z = Z0 + Z1, T = T0 + T1;
#pragma unroll
        for (int o = 16; o; o >>= 1) {
            Z += __shfl_xor_sync(0xffffffffu, Z, o);
            T += __shfl_xor_sync(0xffffffffu, T, o);
        }
        if (l == 0) { u.e.Z[w] = Z; u.e.T[w] = T; }
        __syncthreads();
        if (w == 0) {
            float ZZ = (l < 8) ? u.e.Z[l] : 0.f;
            float TT = (l < 8) ? u.e.T[l] : 0.f;
#pragma unroll
            for (int o = 4; o; o >>= 1) {
                ZZ += __shfl_xor_sync(0xffffffffu, ZZ, o);
                TT += __shfl_xor_sync(0xffffffffu, TT, o);
            }
            if (l == 0) atomicAdd(&g_acc[4], logf(ZZ) - TT / ZZ);
        }
    }

    // ===================== completion: last block packs outputs
    __syncthreads();
    if (tid == 0) {
        __threadfence();
        s_flag = (atomicAdd(&g_done, 1) == GRID_MG - 1);
    }
    __syncthreads();
    if (s_flag) {
        __threadfence();
        volatile float* ga = g_acc;
        if (tid < 4)       out[tid] = ga[tid] * (1.f / (float)B_);
        else if (tid == 4) out[4] = ga[4] * (1.f / (float)B_);
        else if (tid == 5) out[5] = ga[5] * (1.f / (float)(B_ * S_));
    }
}

// ---------------------------------------------------------------- launch
extern "C" void kernel_launch(void* const* d_in, const int* in_sizes, int n_in,
                              void* d_out, int out_size) {
    const float* slots  = (const float*)d_in[0];
    const float* logits = (const float*)d_in[1];
    const float* ln_w   = (const float*)d_in[2];
    const float* ln_b   = (const float*)d_in[3];
    const float* w1     = (const float*)d_in[4];
    const float* b1     = (const float*)d_in[5];
    const float* w2     = (const float*)d_in[6];
    const float* b2     = (const float*)d_in[7];
    float* out = (float*)d_out;

    k_init<<<32, 512>>>();
    k_slots<<<GRID_SL, 512>>>(slots, ln_w, ln_b, w1);
    k_mega<<<GRID_MG, 256>>>(logits, b1, w2, b2, out);
}